// round 13
// baseline (speedup 1.0000x reference)
#include <cuda_runtime.h>
#include <cuda_fp16.h>
#include <cstdint>
#include <math.h>

// Problem constants
#define D_INC   2048
#define D_OUTC  2048
#define NHEADS  16
#define HDIM    128
#define LATENT  256
#define BATCH   2
#define SEQ     2048
#define MTOT    (BATCH * SEQ)        // 4096

#define NEG_BIG (-1.0e30f)
// rsqrt(128) * log2(e)  — folded into q projection; softmax uses ex2
#define QK_SCALE 0.12751875732f
#define H2_ONES  0x3C003C00u
// static softmax shift (log2 domain); exact softmax (constant cancels)
#define SM_SHIFT 4.0f

// ---------------------------------------------------------------------------
// Scratch (device globals; no allocation allowed)
// ---------------------------------------------------------------------------
__device__ __align__(16) __half g_xh  [(size_t)MTOT * D_INC];
__device__ __align__(16) __half g_qh  [(size_t)MTOT * D_OUTC];
__device__ __align__(16) __half g_lath[(size_t)MTOT * LATENT];
__device__ __align__(16) __half g_kvh [(size_t)MTOT * 2 * D_OUTC];
__device__ __align__(16) __half g_ctxh[(size_t)MTOT * D_OUTC];
__device__ __align__(16) __half g_wqd [(size_t)D_INC * (D_OUTC + LATENT)];  // [2048][2304]
__device__ __align__(16) __half g_wukv[(size_t)LATENT * 2 * D_OUTC];        // [256][4096]
__device__ __align__(16) __half g_wout[(size_t)D_OUTC * D_INC];             // [2048][2048]

// ---------------------------------------------------------------------------
// PTX helpers
// ---------------------------------------------------------------------------
__device__ __forceinline__ uint32_t smem_u32(const void* p) {
    uint32_t a;
    asm("{ .reg .u64 t; cvta.to.shared.u64 t, %1; cvt.u32.u64 %0, t; }"
        : "=r"(a) : "l"(p));
    return a;
}
__device__ __forceinline__ uint32_t h2ex2(uint32_t x) {
    uint32_t y;
    asm("ex2.approx.f16x2 %0, %1;" : "=r"(y) : "r"(x));
    return y;
}

#define CP_ASYNC16(dst, src) \
    asm volatile("cp.async.cg.shared.global [%0], [%1], 16;" \
                 :: "r"(dst), "l"(src) : "memory")
#define CP_COMMIT() asm volatile("cp.async.commit_group;" ::: "memory")
#define CP_WAIT1()  asm volatile("cp.async.wait_group 1;" ::: "memory")

#define LDSM_X4(r0, r1, r2, r3, a) \
    asm volatile("ldmatrix.sync.aligned.m8n8.x4.shared.b16 {%0,%1,%2,%3}, [%4];" \
                 : "=r"(r0), "=r"(r1), "=r"(r2), "=r"(r3) : "r"(a))
#define LDSM_X4_T(r0, r1, r2, r3, a) \
    asm volatile("ldmatrix.sync.aligned.m8n8.x4.trans.shared.b16 {%0,%1,%2,%3}, [%4];" \
                 : "=r"(r0), "=r"(r1), "=r"(r2), "=r"(r3) : "r"(a))

#define MMA16816(d, a, b0_, b1_) \
    asm volatile("mma.sync.aligned.m16n8k16.row.col.f32.f16.f16.f32 " \
                 "{%0,%1,%2,%3}, {%4,%5,%6,%7}, {%8,%9}, {%0,%1,%2,%3};" \
                 : "+f"((d)[0]), "+f"((d)[1]), "+f"((d)[2]), "+f"((d)[3]) \
                 : "r"((a)[0]), "r"((a)[1]), "r"((a)[2]), "r"((a)[3]), \
                   "r"(b0_), "r"(b1_))

__device__ __forceinline__ uint32_t swz128(uint32_t r, uint32_t c) {
    return r * 128u + ((c ^ (r & 7u)) << 4);
}
__device__ __forceinline__ uint32_t swz256(uint32_t r, uint32_t c) {
    return r * 256u + ((c ^ (r & 7u)) << 4);
}
__device__ __forceinline__ uint32_t packh2(float a, float b) {
    __half2 h = __floats2half2_rn(a, b);
    return *reinterpret_cast<uint32_t*>(&h);
}

// ---------------------------------------------------------------------------
// fp16 GEMM: C[M,N] = A[M,K] @ B[K,N]   (B row-major [K][N], trans-ldmatrix)
// CTA 128(M) x 128(N), BK=64, 8 warps (4M x 2N), warp tile 32x64.
// 3-stage cp.async pipeline (32KB/stage) -> 2 CTAs/SM.
// ---------------------------------------------------------------------------
#define GSTAGE     32768
#define GEMM_SMEM  (3 * GSTAGE + 1024)

__device__ __forceinline__ void gemm_load_stage(
    uint32_t buf, const __half* __restrict__ A, const __half* __restrict__ B,
    int lda, int ldb, int m0, int n0, int k0, int tid)
{
    const uint32_t bufA = buf, bufB = buf + 16384;
#pragma unroll
    for (int i = 0; i < 4; i++) {
        int f = tid + i * 256;
        int r = f >> 3, c = f & 7;
        CP_ASYNC16(bufA + swz128(r, c),
                   A + (size_t)(m0 + r) * lda + k0 + c * 8);
    }
#pragma unroll
    for (int i = 0; i < 4; i++) {
        int f = tid + i * 256;
        int r = f >> 4, c = f & 15;
        CP_ASYNC16(bufB + swz256(r, c),
                   B + (size_t)(k0 + r) * ldb + n0 + c * 8);
    }
}

__global__ __launch_bounds__(256, 2)
void gemm_h_kernel(const __half* __restrict__ A, const __half* __restrict__ B,
                   const float* __restrict__ bias,
                   void* __restrict__ Cv, int ldc,
                   void* __restrict__ C2v, int ldc2, int nsplit,
                   int K, int lda, int ldb, int fp32out, float cscale, int mbase)
{
    extern __shared__ char smem_raw[];
    uint32_t sb = (smem_u32(smem_raw) + 1023u) & ~1023u;

    const int tid  = threadIdx.x;
    const int wid  = tid >> 5;
    const int lane = tid & 31;
    const int wm   = wid & 3;
    const int wn   = wid >> 2;
    const int g    = lane >> 2;
    const int tig  = lane & 3;
    const int m0 = (blockIdx.y + mbase) * 128;
    const int n0 = blockIdx.x * 128;

    float acc[2][8][4];
#pragma unroll
    for (int mt = 0; mt < 2; mt++)
#pragma unroll
        for (int nt = 0; nt < 8; nt++)
#pragma unroll
            for (int e = 0; e < 4; e++) acc[mt][nt][e] = 0.f;

    const uint32_t a_row  = wm * 32 + (lane & 15);
    const uint32_t a_chb  = lane >> 4;
    const uint32_t bt_row = (((lane >> 3) & 1) << 3) + (lane & 7);
    const uint32_t bt_chb = lane >> 4;

    const int S = K >> 6;

    gemm_load_stage(sb,          A, B, lda, ldb, m0, n0, 0,  tid); CP_COMMIT();
    gemm_load_stage(sb + GSTAGE, A, B, lda, ldb, m0, n0, 64, tid); CP_COMMIT();

    for (int s = 0; s < S; s++) {
        CP_WAIT1();
        __syncthreads();
        if (s + 2 < S) {
            int bi = s + 2 - 3 * ((s + 2) / 3);
            gemm_load_stage(sb + bi * GSTAGE,
                            A, B, lda, ldb, m0, n0, (s + 2) * 64, tid);
        }
        CP_COMMIT();

        const int sbi = s - 3 * (s / 3);
        const uint32_t bA = sb + sbi * GSTAGE;
        const uint32_t bB = bA + 16384;

#pragma unroll
        for (int kt = 0; kt < 4; kt++) {
            uint32_t af[2][4], bf[8][2];
#pragma unroll
            for (int mt = 0; mt < 2; mt++)
                LDSM_X4(af[mt][0], af[mt][1], af[mt][2], af[mt][3],
                        bA + swz128(a_row + mt * 16, kt * 2 + a_chb));
#pragma unroll
            for (int np = 0; np < 4; np++) {
                uint32_t r0, r1, r2, r3;
                LDSM_X4_T(r0, r1, r2, r3,
                          bB + swz256(kt * 16 + bt_row,
                                      (uint32_t)(wn * 8 + np * 2) + bt_chb));
                bf[2 * np][0] = r0; bf[2 * np][1] = r1;
                bf[2 * np + 1][0] = r2; bf[2 * np + 1][1] = r3;
            }
#pragma unroll
            for (int mt = 0; mt < 2; mt++)
#pragma unroll
                for (int nt = 0; nt < 8; nt++)
                    MMA16816(acc[mt][nt], af[mt], bf[nt][0], bf[nt][1]);
        }
    }

    // Epilogue
#pragma unroll
    for (int mt = 0; mt < 2; mt++) {
#pragma unroll
        for (int nt = 0; nt < 8; nt++) {
            int row = m0 + wm * 32 + mt * 16 + g;
            int col = n0 + wn * 64 + nt * 8 + 2 * tig;
            float* a = acc[mt][nt];
            if (fp32out) {
                float* C = (float*)Cv;
                float b0 = bias ? bias[col]     : 0.f;
                float b1 = bias ? bias[col + 1] : 0.f;
                *(float2*)(C + (size_t)row * ldc + col) =
                    make_float2(a[0] + b0, a[1] + b1);
                *(float2*)(C + (size_t)(row + 8) * ldc + col) =
                    make_float2(a[2] + b0, a[3] + b1);
            } else if (col < nsplit) {
                __half* C = (__half*)Cv;
                *(uint32_t*)(C + (size_t)row * ldc + col) =
                    packh2(a[0] * cscale, a[1] * cscale);
                *(uint32_t*)(C + (size_t)(row + 8) * ldc + col) =
                    packh2(a[2] * cscale, a[3] * cscale);
            } else {
                __half* C = (__half*)C2v;
                int c2 = col - nsplit;
                *(uint32_t*)(C + (size_t)row * ldc2 + c2)       = packh2(a[0], a[1]);
                *(uint32_t*)(C + (size_t)(row + 8) * ldc2 + c2) = packh2(a[2], a[3]);
            }
        }
    }
}

// ---------------------------------------------------------------------------
// Flash attention, fp16 mma.sync, causal. BQ=128, BK=128, 8 warps x 16 rows.
// Static-shift softmax (exact; constant shift cancels in normalization).
// ---------------------------------------------------------------------------
#define ATTN_SMEM (163840 + 1024)

__global__ __launch_bounds__(256, 1)
void attn_h_kernel(const __half* __restrict__ qh, const __half* __restrict__ kvh,
                   __half* __restrict__ ctxh, int bsel)
{
    extern __shared__ char smem_raw[];
    uint32_t sb = (smem_u32(smem_raw) + 1023u) & ~1023u;
    const uint32_t Qs  = sb;
    const uint32_t KB0 = sb + 32768;
    const uint32_t VB0 = sb + 65536;
    const uint32_t KB1 = sb + 98304;
    const uint32_t VB1 = sb + 131072;

    const int tid  = threadIdx.x;
    const int wq   = tid >> 5;
    const int lane = tid & 31;
    const int g    = lane >> 2;
    const int tig  = lane & 3;
    const int qb = gridDim.x - 1 - blockIdx.x;   // heavy tiles first
    const int h  = blockIdx.y;
    const int b  = bsel;

    const int qrow0 = qb * 128;
    const size_t qrowg  = (size_t)b * SEQ + qrow0;
    const size_t kvrowg = (size_t)b * SEQ;

#pragma unroll
    for (int i = 0; i < 8; i++) {
        int f = tid + i * 256;
        int r = f >> 4, c = f & 15;
        CP_ASYNC16(Qs + swz256(r, c),
                   qh + (qrowg + r) * D_OUTC + h * HDIM + c * 8);
        const __half* src = kvh + (kvrowg + r) * (2 * D_OUTC) + h * HDIM + c * 8;
        CP_ASYNC16(KB0 + swz256(r, c), src);
        CP_ASYNC16(VB0 + swz256(r, c), src + D_OUTC);
    }
    CP_COMMIT();

    float ob[16][4];
#pragma unroll
    for (int nt = 0; nt < 16; nt++)
#pragma unroll
        for (int e = 0; e < 4; e++) ob[nt][e] = 0.f;
    float lacc[4] = {0.f, 0.f, 0.f, 0.f};
    uint32_t qf[8][4];
    const int grA = qrow0 + wq * 16 + g;
    const int grB = grA + 8;

    const uint32_t k_rowb = ((lane >> 4) << 3) + (lane & 7);
    const uint32_t k_chb  = (lane >> 3) & 1;
    const uint32_t v_rowb = (((lane >> 3) & 1) << 3) + (lane & 7);
    const uint32_t v_chb  = lane >> 4;

    for (int kb = 0; kb <= qb; kb++) {
        __syncthreads();
        if (kb + 1 <= qb) {
            const uint32_t nK = ((kb + 1) & 1) ? KB1 : KB0;
            const uint32_t nV = ((kb + 1) & 1) ? VB1 : VB0;
#pragma unroll
            for (int i = 0; i < 8; i++) {
                int f = tid + i * 256;
                int r = f >> 4, c = f & 15;
                const __half* src = kvh + (kvrowg + (size_t)(kb + 1) * 128 + r) * (2 * D_OUTC)
                                    + h * HDIM + c * 8;
                CP_ASYNC16(nK + swz256(r, c), src);
                CP_ASYNC16(nV + swz256(r, c), src + D_OUTC);
            }
        }
        CP_COMMIT();
        CP_WAIT1();
        __syncthreads();

        if (kb == 0) {
#pragma unroll
            for (int kt = 0; kt < 8; kt++) {
                uint32_t row = wq * 16 + (lane & 15);
                uint32_t ch  = kt * 2 + (lane >> 4);
                LDSM_X4(qf[kt][0], qf[kt][1], qf[kt][2], qf[kt][3],
                        Qs + swz256(row, ch));
            }
        }

        const uint32_t Kbuf = (kb & 1) ? KB1 : KB0;
        const uint32_t Vbuf = (kb & 1) ? VB1 : VB0;

        // ---- S = Q @ K^T, pipelined LDSM ----
        float sc[16][4];
#pragma unroll
        for (int nt = 0; nt < 16; nt++)
#pragma unroll
            for (int e = 0; e < 4; e++) sc[nt][e] = 0.f;

        uint32_t kr[2][4];
        LDSM_X4(kr[0][0], kr[0][1], kr[0][2], kr[0][3],
                Kbuf + swz256(k_rowb, k_chb));
#pragma unroll
        for (int np = 0; np < 8; np++) {
#pragma unroll
            for (int kt = 0; kt < 8; kt++) {
                const int idx = np * 8 + kt;
                const int cur = idx & 1, nxt = cur ^ 1;
                if (idx < 63) {
                    const int ni = idx + 1;
                    const uint32_t nrow = (uint32_t)(ni >> 3) * 16 + k_rowb;
                    const uint32_t nch  = (uint32_t)(ni & 7) * 2 + k_chb;
                    LDSM_X4(kr[nxt][0], kr[nxt][1], kr[nxt][2], kr[nxt][3],
                            Kbuf + swz256(nrow, nch));
                }
                MMA16816(sc[2 * np],     qf[kt], kr[cur][0], kr[cur][1]);
                MMA16816(sc[2 * np + 1], qf[kt], kr[cur][2], kr[cur][3]);
            }
        }

        // causal mask (diagonal block only; scores in log2 domain)
        if (kb == qb) {
#pragma unroll
            for (int nt = 0; nt < 16; nt++) {
                int c0 = kb * 128 + nt * 8 + 2 * tig;
                if (c0     > grA) sc[nt][0] = NEG_BIG;
                if (c0 + 1 > grA) sc[nt][1] = NEG_BIG;
                if (c0     > grB) sc[nt][2] = NEG_BIG;
                if (c0 + 1 > grB) sc[nt][3] = NEG_BIG;
            }
        }

        // P fragments: 2^(s - SHIFT) directly in fp16x2
        uint32_t pa[8][4];
#pragma unroll
        for (int kt = 0; kt < 8; kt++) {
            pa[kt][0] = h2ex2(packh2(sc[2 * kt][0] - SM_SHIFT,
                                     sc[2 * kt][1] - SM_SHIFT));
            pa[kt][1] = h2ex2(packh2(sc[2 * kt][2] - SM_SHIFT,
                                     sc[2 * kt][3] - SM_SHIFT));
            pa[kt][2] = h2ex2(packh2(sc[2 * kt + 1][0] - SM_SHIFT,
                                     sc[2 * kt + 1][1] - SM_SHIFT));
            pa[kt][3] = h2ex2(packh2(sc[2 * kt + 1][2] - SM_SHIFT,
                                     sc[2 * kt + 1][3] - SM_SHIFT));
        }

        // row sums on the tensor pipe: lacc += P @ ones
#pragma unroll
        for (int kt = 0; kt < 8; kt++)
            MMA16816(lacc, pa[kt], H2_ONES, H2_ONES);

        // ---- O += P @ V, pipelined LDSM_T ----
        uint32_t vr[2][4];
        LDSM_X4_T(vr[0][0], vr[0][1], vr[0][2], vr[0][3],
                  Vbuf + swz256(v_rowb, v_chb));
#pragma unroll
        for (int np = 0; np < 8; np++) {
#pragma unroll
            for (int kt = 0; kt < 8; kt++) {
                const int idx = np * 8 + kt;
                const int cur = idx & 1, nxt = cur ^ 1;
                if (idx < 63) {
                    const int ni = idx + 1;
                    const uint32_t nrow = (uint32_t)(ni & 7) * 16 + v_rowb;
                    const uint32_t nch  = (uint32_t)(ni >> 3) * 2 + v_chb;
                    LDSM_X4_T(vr[nxt][0], vr[nxt][1], vr[nxt][2], vr[nxt][3],
                              Vbuf + swz256(nrow, nch));
                }
                MMA16816(ob[2 * np],     pa[kt], vr[cur][0], vr[cur][1]);
                MMA16816(ob[2 * np + 1], pa[kt], vr[cur][2], vr[cur][3]);
            }
        }
    }

    const float invA = 1.f / lacc[0];
    const float invB = 1.f / lacc[2];
    const size_t rowA = (qrowg + wq * 16 + g) * D_OUTC + h * HDIM;
#pragma unroll
    for (int nt = 0; nt < 16; nt++) {
        int col = nt * 8 + 2 * tig;
        *(uint32_t*)(ctxh + rowA + col) =
            packh2(ob[nt][0] * invA, ob[nt][1] * invA);
        *(uint32_t*)(ctxh + rowA + 8 * D_OUTC + col) =
            packh2(ob[nt][2] * invB, ob[nt][3] * invB);
    }
}

// ---------------------------------------------------------------------------
// fp32 -> fp16 convert-copy, 32B/thread (2x float4); optional column restack
// ---------------------------------------------------------------------------
__global__ void conv_copy_h(const float* __restrict__ in,
                            __half* __restrict__ out,
                            int C, int ldout, int co, int total)
{
    int i = (blockIdx.x * 256 + threadIdx.x) * 8;
    if (i < total) {
        float4 v0 = *reinterpret_cast<const float4*>(in + i);
        float4 v1 = *reinterpret_cast<const float4*>(in + i + 4);
        int r = i / C, c = i - r * C;      // rows are multiples of 8 floats here
        __half2* o = reinterpret_cast<__half2*>(out + (size_t)r * ldout + co + c);
        o[0] = __floats2half2_rn(v0.x, v0.y);
        o[1] = __floats2half2_rn(v0.z, v0.w);
        o[2] = __floats2half2_rn(v1.x, v1.y);
        o[3] = __floats2half2_rn(v1.z, v1.w);
    }
}

// ---------------------------------------------------------------------------
// Launch: two chains; conversion front split by dependency criticality.
// Host order: every EventRecord precedes any WaitEvent that references it.
// ---------------------------------------------------------------------------
extern "C" void kernel_launch(void* const* d_in, const int* in_sizes, int n_in,
                              void* d_out, int out_size)
{
    const float* x    = (const float*)d_in[0];
    const float* Wq   = (const float*)d_in[1];
    const float* Wdkv = (const float*)d_in[2];
    const float* Wukv = (const float*)d_in[3];
    const float* Wout = (const float*)d_in[4];
    const float* bout = (const float*)d_in[5];
    float* out = (float*)d_out;

    __half *xh, *qh, *lath, *kvh, *ctxh, *wqd, *wukv, *wout;
    cudaGetSymbolAddress((void**)&xh,   g_xh);
    cudaGetSymbolAddress((void**)&qh,   g_qh);
    cudaGetSymbolAddress((void**)&lath, g_lath);
    cudaGetSymbolAddress((void**)&kvh,  g_kvh);
    cudaGetSymbolAddress((void**)&ctxh, g_ctxh);
    cudaGetSymbolAddress((void**)&wqd,  g_wqd);
    cudaGetSymbolAddress((void**)&wukv, g_wukv);
    cudaGetSymbolAddress((void**)&wout, g_wout);

    static cudaStream_t s1 = nullptr, s2 = nullptr;
    static cudaEvent_t e0, e_x0, e_wqd, e_ukv, e_wout, e_d1, e_d2;
    if (!s1) {
        cudaStreamCreateWithFlags(&s1, cudaStreamNonBlocking);
        cudaStreamCreateWithFlags(&s2, cudaStreamNonBlocking);
        cudaEventCreateWithFlags(&e0,     cudaEventDisableTiming);
        cudaEventCreateWithFlags(&e_x0,   cudaEventDisableTiming);
        cudaEventCreateWithFlags(&e_wqd,  cudaEventDisableTiming);
        cudaEventCreateWithFlags(&e_ukv,  cudaEventDisableTiming);
        cudaEventCreateWithFlags(&e_wout, cudaEventDisableTiming);
        cudaEventCreateWithFlags(&e_d1,   cudaEventDisableTiming);
        cudaEventCreateWithFlags(&e_d2,   cudaEventDisableTiming);
        cudaFuncSetAttribute(gemm_h_kernel,
                             cudaFuncAttributeMaxDynamicSharedMemorySize, GEMM_SMEM);
        cudaFuncSetAttribute(attn_h_kernel,
                             cudaFuncAttributeMaxDynamicSharedMemorySize, ATTN_SMEM);
    }

    const int HM = MTOT / 2;                 // rows per batch = 2048
    const int HT = HM / 128;                 // 16 M-tiles per batch
    const int HE = HM * D_INC;               // x elements per batch

    // Fork both streams off the capture (null) stream
    cudaEventRecord(e0, 0);
    cudaStreamWaitEvent(s1, e0, 0);
    cudaStreamWaitEvent(s2, e0, 0);

    // ---- s2 front: x0 first (critical for proj0), then x1 ----
    conv_copy_h<<<HE / 2048, 256, 0, s2>>>(x, xh, D_INC, D_INC, 0, HE);
    cudaEventRecord(e_x0, s2);
    conv_copy_h<<<HE / 2048, 256, 0, s2>>>(x + HE, xh + HE, D_INC, D_INC, 0, HE);

    // ---- s1 front: Wq + Wdkv ----
    conv_copy_h<<<(D_INC * D_OUTC) / 2048, 256, 0, s1>>>(
        Wq, wqd, D_OUTC, D_OUTC + LATENT, 0, D_INC * D_OUTC);
    conv_copy_h<<<(D_INC * LATENT) / 2048, 256, 0, s1>>>(
        Wdkv, wqd, LATENT, D_OUTC + LATENT, D_OUTC, D_INC * LATENT);
    cudaEventRecord(e_wqd, s1);

    // ---- s1 chain (batch 0): proj -> Wukv conv -> kv -> attn ----
    cudaStreamWaitEvent(s1, e_x0, 0);                        // e_x0 recorded above
    gemm_h_kernel<<<dim3((D_OUTC + LATENT) / 128, HT), 256, GEMM_SMEM, s1>>>(
        xh, wqd, nullptr, qh, D_OUTC, lath, LATENT, D_OUTC,
        D_INC, D_INC, D_OUTC + LATENT, 0, QK_SCALE, 0);
    conv_copy_h<<<(LATENT * 2 * D_OUTC) / 2048, 256, 0, s1>>>(
        Wukv, wukv, 2 * D_OUTC, 2 * D_OUTC, 0, LATENT * 2 * D_OUTC);
    cudaEventRecord(e_ukv, s1);
    gemm_h_kernel<<<dim3((2 * D_OUTC) / 128, HT), 256, GEMM_SMEM, s1>>>(
        lath, wukv, nullptr, kvh, 2 * D_OUTC, nullptr, 0, 1 << 30,
        LATENT, LATENT, 2 * D_OUTC, 0, 1.0f, 0);
    attn_h_kernel<<<dim3(HT, NHEADS, 1), 256, ATTN_SMEM, s1>>>(qh, kvh, ctxh, 0);

    // ---- s2 chain (batch 1): proj -> Wout conv -> kv -> attn -> out ----
    cudaStreamWaitEvent(s2, e_wqd, 0);                       // e_wqd recorded above
    gemm_h_kernel<<<dim3((D_OUTC + LATENT) / 128, HT), 256, GEMM_SMEM, s2>>>(
        xh, wqd, nullptr, qh, D_OUTC, lath, LATENT, D_OUTC,
        D_INC, D_INC, D_OUTC + LATENT, 0, QK_SCALE, HT);
    conv_copy_h<<<(D_OUTC * D_INC) / 2048, 256, 0, s2>>>(
        Wout, wout, D_INC, D_INC, 0, D_OUTC * D_INC);
    cudaEventRecord(e_wout, s2);
    cudaStreamWaitEvent(s2, e_ukv, 0);                       // e_ukv recorded above
    gemm_h_kernel<<<dim3((2 * D_OUTC) / 128, HT), 256, GEMM_SMEM, s2>>>(
        lath, wukv, nullptr, kvh, 2 * D_OUTC, nullptr, 0, 1 << 30,
        LATENT, LATENT, 2 * D_OUTC, 0, 1.0f, HT);
    attn_h_kernel<<<dim3(HT, NHEADS, 1), 256, ATTN_SMEM, s2>>>(qh, kvh, ctxh, 1);
    gemm_h_kernel<<<dim3(D_INC / 128, HT), 256, GEMM_SMEM, s2>>>(
        ctxh, wout, bout, out, D_INC, nullptr, 0, 1 << 30,
        D_OUTC, D_OUTC, D_INC, 1, 1.0f, HT);
    cudaEventRecord(e_d2, s2);

    // ---- s1 tail: out (needs Wout) ----
    cudaStreamWaitEvent(s1, e_wout, 0);                      // e_wout recorded above
    gemm_h_kernel<<<dim3(D_INC / 128, HT), 256, GEMM_SMEM, s1>>>(
        ctxh, wout, bout, out, D_INC, nullptr, 0, 1 << 30,
        D_OUTC, D_OUTC, D_INC, 1, 1.0f, 0);
    cudaEventRecord(e_d1, s1);

    // Join back into the capture stream
    cudaStreamWaitEvent(0, e_d1, 0);
    cudaStreamWaitEvent(0, e_d2, 0);
}

// round 14
// speedup vs baseline: 1.0010x; 1.0010x over previous
#include <cuda_runtime.h>
#include <cuda_fp16.h>
#include <cstdint>
#include <math.h>

// Problem constants
#define D_INC   2048
#define D_OUTC  2048
#define NHEADS  16
#define HDIM    128
#define LATENT  256
#define BATCH   2
#define SEQ     2048
#define MTOT    (BATCH * SEQ)        // 4096

#define NEG_BIG (-1.0e30f)
// rsqrt(128) * log2(e)  — folded into q projection; softmax uses ex2
#define QK_SCALE 0.12751875732f
#define H2_ONES  0x3C003C00u
// static softmax shift (log2 domain); exact softmax (constant cancels)
#define SM_SHIFT 4.0f

// ---------------------------------------------------------------------------
// Scratch (device globals; no allocation allowed)
// ---------------------------------------------------------------------------
__device__ __align__(16) __half g_xh  [(size_t)MTOT * D_INC];
__device__ __align__(16) __half g_qh  [(size_t)MTOT * D_OUTC];
__device__ __align__(16) __half g_lath[(size_t)MTOT * LATENT];
__device__ __align__(16) __half g_kvh [(size_t)MTOT * 2 * D_OUTC];
__device__ __align__(16) __half g_ctxh[(size_t)MTOT * D_OUTC];
__device__ __align__(16) __half g_wqd [(size_t)D_INC * (D_OUTC + LATENT)];  // [2048][2304]
__device__ __align__(16) __half g_wukv[(size_t)LATENT * 2 * D_OUTC];        // [256][4096]
__device__ __align__(16) __half g_wout[(size_t)D_OUTC * D_INC];             // [2048][2048]

// ---------------------------------------------------------------------------
// PTX helpers
// ---------------------------------------------------------------------------
__device__ __forceinline__ uint32_t smem_u32(const void* p) {
    uint32_t a;
    asm("{ .reg .u64 t; cvta.to.shared.u64 t, %1; cvt.u32.u64 %0, t; }"
        : "=r"(a) : "l"(p));
    return a;
}
__device__ __forceinline__ uint32_t h2ex2(uint32_t x) {
    uint32_t y;
    asm("ex2.approx.f16x2 %0, %1;" : "=r"(y) : "r"(x));
    return y;
}

#define CP_ASYNC16(dst, src) \
    asm volatile("cp.async.cg.shared.global [%0], [%1], 16;" \
                 :: "r"(dst), "l"(src) : "memory")
#define CP_COMMIT() asm volatile("cp.async.commit_group;" ::: "memory")
#define CP_WAIT1()  asm volatile("cp.async.wait_group 1;" ::: "memory")

#define LDSM_X4(r0, r1, r2, r3, a) \
    asm volatile("ldmatrix.sync.aligned.m8n8.x4.shared.b16 {%0,%1,%2,%3}, [%4];" \
                 : "=r"(r0), "=r"(r1), "=r"(r2), "=r"(r3) : "r"(a))
#define LDSM_X4_T(r0, r1, r2, r3, a) \
    asm volatile("ldmatrix.sync.aligned.m8n8.x4.trans.shared.b16 {%0,%1,%2,%3}, [%4];" \
                 : "=r"(r0), "=r"(r1), "=r"(r2), "=r"(r3) : "r"(a))

#define MMA16816(d, a, b0_, b1_) \
    asm volatile("mma.sync.aligned.m16n8k16.row.col.f32.f16.f16.f32 " \
                 "{%0,%1,%2,%3}, {%4,%5,%6,%7}, {%8,%9}, {%0,%1,%2,%3};" \
                 : "+f"((d)[0]), "+f"((d)[1]), "+f"((d)[2]), "+f"((d)[3]) \
                 : "r"((a)[0]), "r"((a)[1]), "r"((a)[2]), "r"((a)[3]), \
                   "r"(b0_), "r"(b1_))

__device__ __forceinline__ uint32_t swz128(uint32_t r, uint32_t c) {
    return r * 128u + ((c ^ (r & 7u)) << 4);
}
__device__ __forceinline__ uint32_t swz256(uint32_t r, uint32_t c) {
    return r * 256u + ((c ^ (r & 7u)) << 4);
}
__device__ __forceinline__ uint32_t packh2(float a, float b) {
    __half2 h = __floats2half2_rn(a, b);
    return *reinterpret_cast<uint32_t*>(&h);
}

// ---------------------------------------------------------------------------
// fp16 GEMM: C[M,N] = A[M,K] @ B[K,N]   (B row-major [K][N], trans-ldmatrix)
// CTA 128(M) x 128(N), BK=64, 8 warps (4M x 2N), warp tile 32x64.
// 3-stage cp.async pipeline (32KB/stage) -> 2 CTAs/SM.
// ---------------------------------------------------------------------------
#define GSTAGE     32768
#define GEMM_SMEM  (3 * GSTAGE + 1024)

__device__ __forceinline__ void gemm_load_stage(
    uint32_t buf, const __half* __restrict__ A, const __half* __restrict__ B,
    int lda, int ldb, int m0, int n0, int k0, int tid)
{
    const uint32_t bufA = buf, bufB = buf + 16384;
#pragma unroll
    for (int i = 0; i < 4; i++) {
        int f = tid + i * 256;
        int r = f >> 3, c = f & 7;
        CP_ASYNC16(bufA + swz128(r, c),
                   A + (size_t)(m0 + r) * lda + k0 + c * 8);
    }
#pragma unroll
    for (int i = 0; i < 4; i++) {
        int f = tid + i * 256;
        int r = f >> 4, c = f & 15;
        CP_ASYNC16(bufB + swz256(r, c),
                   B + (size_t)(k0 + r) * ldb + n0 + c * 8);
    }
}

__global__ __launch_bounds__(256, 2)
void gemm_h_kernel(const __half* __restrict__ A, const __half* __restrict__ B,
                   const float* __restrict__ bias,
                   void* __restrict__ Cv, int ldc,
                   void* __restrict__ C2v, int ldc2, int nsplit,
                   int K, int lda, int ldb, int fp32out, float cscale, int mbase)
{
    extern __shared__ char smem_raw[];
    uint32_t sb = (smem_u32(smem_raw) + 1023u) & ~1023u;

    const int tid  = threadIdx.x;
    const int wid  = tid >> 5;
    const int lane = tid & 31;
    const int wm   = wid & 3;
    const int wn   = wid >> 2;
    const int g    = lane >> 2;
    const int tig  = lane & 3;
    const int m0 = (blockIdx.y + mbase) * 128;
    const int n0 = blockIdx.x * 128;

    float acc[2][8][4];
#pragma unroll
    for (int mt = 0; mt < 2; mt++)
#pragma unroll
        for (int nt = 0; nt < 8; nt++)
#pragma unroll
            for (int e = 0; e < 4; e++) acc[mt][nt][e] = 0.f;

    const uint32_t a_row  = wm * 32 + (lane & 15);
    const uint32_t a_chb  = lane >> 4;
    const uint32_t bt_row = (((lane >> 3) & 1) << 3) + (lane & 7);
    const uint32_t bt_chb = lane >> 4;

    const int S = K >> 6;

    gemm_load_stage(sb,          A, B, lda, ldb, m0, n0, 0,  tid); CP_COMMIT();
    gemm_load_stage(sb + GSTAGE, A, B, lda, ldb, m0, n0, 64, tid); CP_COMMIT();

    for (int s = 0; s < S; s++) {
        CP_WAIT1();
        __syncthreads();
        if (s + 2 < S) {
            int bi = s + 2 - 3 * ((s + 2) / 3);
            gemm_load_stage(sb + bi * GSTAGE,
                            A, B, lda, ldb, m0, n0, (s + 2) * 64, tid);
        }
        CP_COMMIT();

        const int sbi = s - 3 * (s / 3);
        const uint32_t bA = sb + sbi * GSTAGE;
        const uint32_t bB = bA + 16384;

#pragma unroll
        for (int kt = 0; kt < 4; kt++) {
            uint32_t af[2][4], bf[8][2];
#pragma unroll
            for (int mt = 0; mt < 2; mt++)
                LDSM_X4(af[mt][0], af[mt][1], af[mt][2], af[mt][3],
                        bA + swz128(a_row + mt * 16, kt * 2 + a_chb));
#pragma unroll
            for (int np = 0; np < 4; np++) {
                uint32_t r0, r1, r2, r3;
                LDSM_X4_T(r0, r1, r2, r3,
                          bB + swz256(kt * 16 + bt_row,
                                      (uint32_t)(wn * 8 + np * 2) + bt_chb));
                bf[2 * np][0] = r0; bf[2 * np][1] = r1;
                bf[2 * np + 1][0] = r2; bf[2 * np + 1][1] = r3;
            }
#pragma unroll
            for (int mt = 0; mt < 2; mt++)
#pragma unroll
                for (int nt = 0; nt < 8; nt++)
                    MMA16816(acc[mt][nt], af[mt], bf[nt][0], bf[nt][1]);
        }
    }

    // Epilogue
#pragma unroll
    for (int mt = 0; mt < 2; mt++) {
#pragma unroll
        for (int nt = 0; nt < 8; nt++) {
            int row = m0 + wm * 32 + mt * 16 + g;
            int col = n0 + wn * 64 + nt * 8 + 2 * tig;
            float* a = acc[mt][nt];
            if (fp32out) {
                float* C = (float*)Cv;
                float b0 = bias ? bias[col]     : 0.f;
                float b1 = bias ? bias[col + 1] : 0.f;
                *(float2*)(C + (size_t)row * ldc + col) =
                    make_float2(a[0] + b0, a[1] + b1);
                *(float2*)(C + (size_t)(row + 8) * ldc + col) =
                    make_float2(a[2] + b0, a[3] + b1);
            } else if (col < nsplit) {
                __half* C = (__half*)Cv;
                *(uint32_t*)(C + (size_t)row * ldc + col) =
                    packh2(a[0] * cscale, a[1] * cscale);
                *(uint32_t*)(C + (size_t)(row + 8) * ldc + col) =
                    packh2(a[2] * cscale, a[3] * cscale);
            } else {
                __half* C = (__half*)C2v;
                int c2 = col - nsplit;
                *(uint32_t*)(C + (size_t)row * ldc2 + c2)       = packh2(a[0], a[1]);
                *(uint32_t*)(C + (size_t)(row + 8) * ldc2 + c2) = packh2(a[2], a[3]);
            }
        }
    }
}

// ---------------------------------------------------------------------------
// Flash attention, fp16 mma.sync, causal. BQ=128, BK=128, 8 warps x 16 rows.
// Static-shift softmax. 3-stage KV ring: ONE barrier per KV block (the
// visibility barrier also orders prior reads of the ring slot being refilled).
// smem: Q 32KB + 3 x (K 32KB + V 32KB) = 224KB.
// ---------------------------------------------------------------------------
#define ATTN_SMEM (229376 + 1024)

__global__ __launch_bounds__(256, 1)
void attn_h_kernel(const __half* __restrict__ qh, const __half* __restrict__ kvh,
                   __half* __restrict__ ctxh, int bsel)
{
    extern __shared__ char smem_raw[];
    uint32_t sb = (smem_u32(smem_raw) + 1023u) & ~1023u;
    const uint32_t Qs = sb;
    // ring slot s: K at sb+32768+s*65536, V 32KB above it

    const int tid  = threadIdx.x;
    const int wq   = tid >> 5;
    const int lane = tid & 31;
    const int g    = lane >> 2;
    const int tig  = lane & 3;
    const int qb = gridDim.x - 1 - blockIdx.x;   // heavy tiles first
    const int h  = blockIdx.y;
    const int b  = bsel;

    const int qrow0 = qb * 128;
    const size_t qrowg  = (size_t)b * SEQ + qrow0;
    const size_t kvrowg = (size_t)b * SEQ;

    // Prologue: Q + KV stage0 (group 0)
#pragma unroll
    for (int i = 0; i < 8; i++) {
        int f = tid + i * 256;
        int r = f >> 4, c = f & 15;
        CP_ASYNC16(Qs + swz256(r, c),
                   qh + (qrowg + r) * D_OUTC + h * HDIM + c * 8);
        const __half* src = kvh + (kvrowg + r) * (2 * D_OUTC) + h * HDIM + c * 8;
        CP_ASYNC16(sb + 32768 + swz256(r, c), src);
        CP_ASYNC16(sb + 65536 + swz256(r, c), src + D_OUTC);
    }
    CP_COMMIT();
    // KV stage1 (group 1), if needed
    if (qb >= 1) {
#pragma unroll
        for (int i = 0; i < 8; i++) {
            int f = tid + i * 256;
            int r = f >> 4, c = f & 15;
            const __half* src = kvh + (kvrowg + 128 + r) * (2 * D_OUTC)
                                + h * HDIM + c * 8;
            CP_ASYNC16(sb + 98304 + swz256(r, c), src);
            CP_ASYNC16(sb + 131072 + swz256(r, c), src + D_OUTC);
        }
    }
    CP_COMMIT();

    float ob[16][4];
#pragma unroll
    for (int nt = 0; nt < 16; nt++)
#pragma unroll
        for (int e = 0; e < 4; e++) ob[nt][e] = 0.f;
    float lacc[4] = {0.f, 0.f, 0.f, 0.f};
    uint32_t qf[8][4];
    const int grA = qrow0 + wq * 16 + g;
    const int grB = grA + 8;

    const uint32_t k_rowb = ((lane >> 4) << 3) + (lane & 7);
    const uint32_t k_chb  = (lane >> 3) & 1;
    const uint32_t v_rowb = (((lane >> 3) & 1) << 3) + (lane & 7);
    const uint32_t v_chb  = lane >> 4;

    int cslot = 0;    // ring slot for current stage kb
    int pslot = 2;    // ring slot for prefetch stage kb+2

    for (int kb = 0; kb <= qb; kb++) {
        CP_WAIT1();          // oldest pending group = stage kb -> resident
        __syncthreads();     // visibility + orders prior reads of slot pslot

        if (kb + 2 <= qb) {
            const uint32_t nK = sb + 32768 + (uint32_t)pslot * 65536;
            const uint32_t nV = nK + 32768;
#pragma unroll
            for (int i = 0; i < 8; i++) {
                int f = tid + i * 256;
                int r = f >> 4, c = f & 15;
                const __half* src = kvh + (kvrowg + (size_t)(kb + 2) * 128 + r) * (2 * D_OUTC)
                                    + h * HDIM + c * 8;
                CP_ASYNC16(nK + swz256(r, c), src);
                CP_ASYNC16(nV + swz256(r, c), src + D_OUTC);
            }
        }
        CP_COMMIT();         // exactly one group per iteration (may be empty)

        if (kb == 0) {
#pragma unroll
            for (int kt = 0; kt < 8; kt++) {
                uint32_t row = wq * 16 + (lane & 15);
                uint32_t ch  = kt * 2 + (lane >> 4);
                LDSM_X4(qf[kt][0], qf[kt][1], qf[kt][2], qf[kt][3],
                        Qs + swz256(row, ch));
            }
        }

        const uint32_t Kbuf = sb + 32768 + (uint32_t)cslot * 65536;
        const uint32_t Vbuf = Kbuf + 32768;

        // ---- S = Q @ K^T, pipelined LDSM ----
        float sc[16][4];
#pragma unroll
        for (int nt = 0; nt < 16; nt++)
#pragma unroll
            for (int e = 0; e < 4; e++) sc[nt][e] = 0.f;

        uint32_t kr[2][4];
        LDSM_X4(kr[0][0], kr[0][1], kr[0][2], kr[0][3],
                Kbuf + swz256(k_rowb, k_chb));
#pragma unroll
        for (int np = 0; np < 8; np++) {
#pragma unroll
            for (int kt = 0; kt < 8; kt++) {
                const int idx = np * 8 + kt;
                const int cur = idx & 1, nxt = cur ^ 1;
                if (idx < 63) {
                    const int ni = idx + 1;
                    const uint32_t nrow = (uint32_t)(ni >> 3) * 16 + k_rowb;
                    const uint32_t nch  = (uint32_t)(ni & 7) * 2 + k_chb;
                    LDSM_X4(kr[nxt][0], kr[nxt][1], kr[nxt][2], kr[nxt][3],
                            Kbuf + swz256(nrow, nch));
                }
                MMA16816(sc[2 * np],     qf[kt], kr[cur][0], kr[cur][1]);
                MMA16816(sc[2 * np + 1], qf[kt], kr[cur][2], kr[cur][3]);
            }
        }

        // causal mask (diagonal block only; scores in log2 domain)
        if (kb == qb) {
#pragma unroll
            for (int nt = 0; nt < 16; nt++) {
                int c0 = kb * 128 + nt * 8 + 2 * tig;
                if (c0     > grA) sc[nt][0] = NEG_BIG;
                if (c0 + 1 > grA) sc[nt][1] = NEG_BIG;
                if (c0     > grB) sc[nt][2] = NEG_BIG;
                if (c0 + 1 > grB) sc[nt][3] = NEG_BIG;
            }
        }

        // P fragments: 2^(s - SHIFT) directly in fp16x2
        uint32_t pa[8][4];
#pragma unroll
        for (int kt = 0; kt < 8; kt++) {
            pa[kt][0] = h2ex2(packh2(sc[2 * kt][0] - SM_SHIFT,
                                     sc[2 * kt][1] - SM_SHIFT));
            pa[kt][1] = h2ex2(packh2(sc[2 * kt][2] - SM_SHIFT,
                                     sc[2 * kt][3] - SM_SHIFT));
            pa[kt][2] = h2ex2(packh2(sc[2 * kt + 1][0] - SM_SHIFT,
                                     sc[2 * kt + 1][1] - SM_SHIFT));
            pa[kt][3] = h2ex2(packh2(sc[2 * kt + 1][2] - SM_SHIFT,
                                     sc[2 * kt + 1][3] - SM_SHIFT));
        }

        // row sums on the tensor pipe: lacc += P @ ones
#pragma unroll
        for (int kt = 0; kt < 8; kt++)
            MMA16816(lacc, pa[kt], H2_ONES, H2_ONES);

        // ---- O += P @ V, pipelined LDSM_T ----
        uint32_t vr[2][4];
        LDSM_X4_T(vr[0][0], vr[0][1], vr[0][2], vr[0][3],
                  Vbuf + swz256(v_rowb, v_chb));
#pragma unroll
        for (int np = 0; np < 8; np++) {
#pragma unroll
            for (int kt = 0; kt < 8; kt++) {
                const int idx = np * 8 + kt;
                const int cur = idx & 1, nxt = cur ^ 1;
                if (idx < 63) {
                    const int ni = idx + 1;
                    const uint32_t nrow = (uint32_t)(ni & 7) * 16 + v_rowb;
                    const uint32_t nch  = (uint32_t)(ni >> 3) * 2 + v_chb;
                    LDSM_X4_T(vr[nxt][0], vr[nxt][1], vr[nxt][2], vr[nxt][3],
                              Vbuf + swz256(nrow, nch));
                }
                MMA16816(ob[2 * np],     pa[kt], vr[cur][0], vr[cur][1]);
                MMA16816(ob[2 * np + 1], pa[kt], vr[cur][2], vr[cur][3]);
            }
        }

        cslot = (cslot == 2) ? 0 : cslot + 1;
        pslot = (pslot == 2) ? 0 : pslot + 1;
    }

    const float invA = 1.f / lacc[0];
    const float invB = 1.f / lacc[2];
    const size_t rowA = (qrowg + wq * 16 + g) * D_OUTC + h * HDIM;
#pragma unroll
    for (int nt = 0; nt < 16; nt++) {
        int col = nt * 8 + 2 * tig;
        *(uint32_t*)(ctxh + rowA + col) =
            packh2(ob[nt][0] * invA, ob[nt][1] * invA);
        *(uint32_t*)(ctxh + rowA + 8 * D_OUTC + col) =
            packh2(ob[nt][2] * invB, ob[nt][3] * invB);
    }
}

// ---------------------------------------------------------------------------
// fp32 -> fp16 convert-copy (coalesced; optional column restack)
// ---------------------------------------------------------------------------
__global__ void conv_copy_h(const float* __restrict__ in,
                            __half* __restrict__ out,
                            int C, int ldout, int co, int total)
{
    int i = (blockIdx.x * 256 + threadIdx.x) * 4;
    if (i < total) {
        float4 v = *reinterpret_cast<const float4*>(in + i);
        int r = i / C, c = i - r * C;
        __half2* o = reinterpret_cast<__half2*>(out + (size_t)r * ldout + co + c);
        o[0] = __floats2half2_rn(v.x, v.y);
        o[1] = __floats2half2_rn(v.z, v.w);
    }
}

// ---------------------------------------------------------------------------
// Launch: two per-batch chains on two streams (exact R8/R12 topology)
// ---------------------------------------------------------------------------
extern "C" void kernel_launch(void* const* d_in, const int* in_sizes, int n_in,
                              void* d_out, int out_size)
{
    const float* x    = (const float*)d_in[0];
    const float* Wq   = (const float*)d_in[1];
    const float* Wdkv = (const float*)d_in[2];
    const float* Wukv = (const float*)d_in[3];
    const float* Wout = (const float*)d_in[4];
    const float* bout = (const float*)d_in[5];
    float* out = (float*)d_out;

    __half *xh, *qh, *lath, *kvh, *ctxh, *wqd, *wukv, *wout;
    cudaGetSymbolAddress((void**)&xh,   g_xh);
    cudaGetSymbolAddress((void**)&qh,   g_qh);
    cudaGetSymbolAddress((void**)&lath, g_lath);
    cudaGetSymbolAddress((void**)&kvh,  g_kvh);
    cudaGetSymbolAddress((void**)&ctxh, g_ctxh);
    cudaGetSymbolAddress((void**)&wqd,  g_wqd);
    cudaGetSymbolAddress((void**)&wukv, g_wukv);
    cudaGetSymbolAddress((void**)&wout, g_wout);

    static cudaStream_t s1 = nullptr, s2 = nullptr;
    static cudaEvent_t e0, e_wqd, e_ukv, e_wout, e_d1, e_d2;
    if (!s1) {
        cudaStreamCreateWithFlags(&s1, cudaStreamNonBlocking);
        cudaStreamCreateWithFlags(&s2, cudaStreamNonBlocking);
        cudaEventCreateWithFlags(&e0,     cudaEventDisableTiming);
        cudaEventCreateWithFlags(&e_wqd,  cudaEventDisableTiming);
        cudaEventCreateWithFlags(&e_ukv,  cudaEventDisableTiming);
        cudaEventCreateWithFlags(&e_wout, cudaEventDisableTiming);
        cudaEventCreateWithFlags(&e_d1,   cudaEventDisableTiming);
        cudaEventCreateWithFlags(&e_d2,   cudaEventDisableTiming);
        cudaFuncSetAttribute(gemm_h_kernel,
                             cudaFuncAttributeMaxDynamicSharedMemorySize, GEMM_SMEM);
        cudaFuncSetAttribute(attn_h_kernel,
                             cudaFuncAttributeMaxDynamicSharedMemorySize, ATTN_SMEM);
    }

    const int HM = MTOT / 2;                 // rows per batch = 2048
    const int HT = HM / 128;                 // 16 M-tiles per batch
    const int HE = HM * D_INC;               // x elements per batch

    // Fork both streams off the capture (null) stream
    cudaEventRecord(e0, 0);
    cudaStreamWaitEvent(s1, e0, 0);
    cudaStreamWaitEvent(s2, e0, 0);

    // ---- S1 front: weights for proj, then batch-0 x ----
    conv_copy_h<<<(D_INC * D_OUTC) / 1024, 256, 0, s1>>>(
        Wq, wqd, D_OUTC, D_OUTC + LATENT, 0, D_INC * D_OUTC);
    conv_copy_h<<<(D_INC * LATENT) / 1024, 256, 0, s1>>>(
        Wdkv, wqd, LATENT, D_OUTC + LATENT, D_OUTC, D_INC * LATENT);
    cudaEventRecord(e_wqd, s1);
    conv_copy_h<<<HE / 1024, 256, 0, s1>>>(x, xh, D_INC, D_INC, 0, HE);

    // ---- S2 front: batch-1 x + other weights ----
    conv_copy_h<<<HE / 1024, 256, 0, s2>>>(x + HE, xh + HE, D_INC, D_INC, 0, HE);
    conv_copy_h<<<(LATENT * 2 * D_OUTC) / 1024, 256, 0, s2>>>(
        Wukv, wukv, 2 * D_OUTC, 2 * D_OUTC, 0, LATENT * 2 * D_OUTC);
    cudaEventRecord(e_ukv, s2);
    conv_copy_h<<<(D_OUTC * D_INC) / 1024, 256, 0, s2>>>(
        Wout, wout, D_INC, D_INC, 0, D_OUTC * D_INC);
    cudaEventRecord(e_wout, s2);

    // ---- S1 chain (batch 0) ----
    gemm_h_kernel<<<dim3((D_OUTC + LATENT) / 128, HT), 256, GEMM_SMEM, s1>>>(
        xh, wqd, nullptr, qh, D_OUTC, lath, LATENT, D_OUTC,
        D_INC, D_INC, D_OUTC + LATENT, 0, QK_SCALE, 0);
    cudaStreamWaitEvent(s1, e_ukv, 0);
    gemm_h_kernel<<<dim3((2 * D_OUTC) / 128, HT), 256, GEMM_SMEM, s1>>>(
        lath, wukv, nullptr, kvh, 2 * D_OUTC, nullptr, 0, 1 << 30,
        LATENT, LATENT, 2 * D_OUTC, 0, 1.0f, 0);
    attn_h_kernel<<<dim3(HT, NHEADS, 1), 256, ATTN_SMEM, s1>>>(qh, kvh, ctxh, 0);
    cudaStreamWaitEvent(s1, e_wout, 0);
    gemm_h_kernel<<<dim3(D_INC / 128, HT), 256, GEMM_SMEM, s1>>>(
        ctxh, wout, bout, out, D_INC, nullptr, 0, 1 << 30,
        D_OUTC, D_OUTC, D_INC, 1, 1.0f, 0);
    cudaEventRecord(e_d1, s1);

    // ---- S2 chain (batch 1) ----
    cudaStreamWaitEvent(s2, e_wqd, 0);
    gemm_h_kernel<<<dim3((D_OUTC + LATENT) / 128, HT), 256, GEMM_SMEM, s2>>>(
        xh, wqd, nullptr, qh, D_OUTC, lath, LATENT, D_OUTC,
        D_INC, D_INC, D_OUTC + LATENT, 0, QK_SCALE, HT);
    gemm_h_kernel<<<dim3((2 * D_OUTC) / 128, HT), 256, GEMM_SMEM, s2>>>(
        lath, wukv, nullptr, kvh, 2 * D_OUTC, nullptr, 0, 1 << 30,
        LATENT, LATENT, 2 * D_OUTC, 0, 1.0f, HT);
    attn_h_kernel<<<dim3(HT, NHEADS, 1), 256, ATTN_SMEM, s2>>>(qh, kvh, ctxh, 1);
    gemm_h_kernel<<<dim3(D_INC / 128, HT), 256, GEMM_SMEM, s2>>>(
        ctxh, wout, bout, out, D_INC, nullptr, 0, 1 << 30,
        D_OUTC, D_OUTC, D_INC, 1, 1.0f, HT);
    cudaEventRecord(e_d2, s2);

    // Join back into the capture stream
    cudaStreamWaitEvent(0, e_d1, 0);
    cudaStreamWaitEvent(0, e_d2, 0);
}

// round 15
// speedup vs baseline: 1.0078x; 1.0068x over previous
#include <cuda_runtime.h>
#include <cuda_fp16.h>
#include <cstdint>
#include <math.h>

// Problem constants
#define D_INC   2048
#define D_OUTC  2048
#define NHEADS  16
#define HDIM    128
#define LATENT  256
#define BATCH   2
#define SEQ     2048
#define MTOT    (BATCH * SEQ)        // 4096

#define NEG_BIG (-1.0e30f)
// rsqrt(128) * log2(e)  — folded into q projection; softmax uses ex2
#define QK_SCALE 0.12751875732f
#define H2_ONES  0x3C003C00u
#define H2_SHIFT 0x44004400u         // half2(4.0, 4.0): static softmax shift
#define H_NINF   0xFC00u             // fp16 -inf

// ---------------------------------------------------------------------------
// Scratch (device globals; no allocation allowed)
// ---------------------------------------------------------------------------
__device__ __align__(16) __half g_xh  [(size_t)MTOT * D_INC];
__device__ __align__(16) __half g_qh  [(size_t)MTOT * D_OUTC];
__device__ __align__(16) __half g_lath[(size_t)MTOT * LATENT];
__device__ __align__(16) __half g_kvh [(size_t)MTOT * 2 * D_OUTC];
__device__ __align__(16) __half g_ctxh[(size_t)MTOT * D_OUTC];
__device__ __align__(16) __half g_wqd [(size_t)D_INC * (D_OUTC + LATENT)];  // [2048][2304]
__device__ __align__(16) __half g_wukv[(size_t)LATENT * 2 * D_OUTC];        // [256][4096]
__device__ __align__(16) __half g_wout[(size_t)D_OUTC * D_INC];             // [2048][2048]

// ---------------------------------------------------------------------------
// PTX helpers
// ---------------------------------------------------------------------------
__device__ __forceinline__ uint32_t smem_u32(const void* p) {
    uint32_t a;
    asm("{ .reg .u64 t; cvta.to.shared.u64 t, %1; cvt.u32.u64 %0, t; }"
        : "=r"(a) : "l"(p));
    return a;
}
__device__ __forceinline__ uint32_t h2ex2(uint32_t x) {
    uint32_t y;
    asm("ex2.approx.f16x2 %0, %1;" : "=r"(y) : "r"(x));
    return y;
}
__device__ __forceinline__ uint32_t h2sub(uint32_t a, uint32_t b) {
    uint32_t d;
    asm("sub.f16x2 %0, %1, %2;" : "=r"(d) : "r"(a), "r"(b));
    return d;
}

#define CP_ASYNC16(dst, src) \
    asm volatile("cp.async.cg.shared.global [%0], [%1], 16;" \
                 :: "r"(dst), "l"(src) : "memory")
#define CP_COMMIT() asm volatile("cp.async.commit_group;" ::: "memory")
#define CP_WAIT1()  asm volatile("cp.async.wait_group 1;" ::: "memory")

#define LDSM_X4(r0, r1, r2, r3, a) \
    asm volatile("ldmatrix.sync.aligned.m8n8.x4.shared.b16 {%0,%1,%2,%3}, [%4];" \
                 : "=r"(r0), "=r"(r1), "=r"(r2), "=r"(r3) : "r"(a))
#define LDSM_X4_T(r0, r1, r2, r3, a) \
    asm volatile("ldmatrix.sync.aligned.m8n8.x4.trans.shared.b16 {%0,%1,%2,%3}, [%4];" \
                 : "=r"(r0), "=r"(r1), "=r"(r2), "=r"(r3) : "r"(a))

// fp32 accumulator MMA
#define MMA16816(d, a, b0_, b1_) \
    asm volatile("mma.sync.aligned.m16n8k16.row.col.f32.f16.f16.f32 " \
                 "{%0,%1,%2,%3}, {%4,%5,%6,%7}, {%8,%9}, {%0,%1,%2,%3};" \
                 : "+f"((d)[0]), "+f"((d)[1]), "+f"((d)[2]), "+f"((d)[3]) \
                 : "r"((a)[0]), "r"((a)[1]), "r"((a)[2]), "r"((a)[3]), \
                   "r"(b0_), "r"(b1_))

// fp16 accumulator MMA (2x rate): d0 = {row g: c0,c1}, d1 = {row g+8: c0,c1}
#define MMA16816_H(d, a, b0_, b1_) \
    asm volatile("mma.sync.aligned.m16n8k16.row.col.f16.f16.f16.f16 " \
                 "{%0,%1}, {%2,%3,%4,%5}, {%6,%7}, {%0,%1};" \
                 : "+r"((d)[0]), "+r"((d)[1]) \
                 : "r"((a)[0]), "r"((a)[1]), "r"((a)[2]), "r"((a)[3]), \
                   "r"(b0_), "r"(b1_))

__device__ __forceinline__ uint32_t swz128(uint32_t r, uint32_t c) {
    return r * 128u + ((c ^ (r & 7u)) << 4);
}
__device__ __forceinline__ uint32_t swz256(uint32_t r, uint32_t c) {
    return r * 256u + ((c ^ (r & 7u)) << 4);
}
__device__ __forceinline__ uint32_t packh2(float a, float b) {
    __half2 h = __floats2half2_rn(a, b);
    return *reinterpret_cast<uint32_t*>(&h);
}

// ---------------------------------------------------------------------------
// fp16 GEMM: C[M,N] = A[M,K] @ B[K,N]   (B row-major [K][N], trans-ldmatrix)
// CTA 128(M) x 128(N), BK=64, 8 warps (4M x 2N), warp tile 32x64.
// 3-stage cp.async pipeline (32KB/stage) -> 2 CTAs/SM.
// ---------------------------------------------------------------------------
#define GSTAGE     32768
#define GEMM_SMEM  (3 * GSTAGE + 1024)

__device__ __forceinline__ void gemm_load_stage(
    uint32_t buf, const __half* __restrict__ A, const __half* __restrict__ B,
    int lda, int ldb, int m0, int n0, int k0, int tid)
{
    const uint32_t bufA = buf, bufB = buf + 16384;
#pragma unroll
    for (int i = 0; i < 4; i++) {
        int f = tid + i * 256;
        int r = f >> 3, c = f & 7;
        CP_ASYNC16(bufA + swz128(r, c),
                   A + (size_t)(m0 + r) * lda + k0 + c * 8);
    }
#pragma unroll
    for (int i = 0; i < 4; i++) {
        int f = tid + i * 256;
        int r = f >> 4, c = f & 15;
        CP_ASYNC16(bufB + swz256(r, c),
                   B + (size_t)(k0 + r) * ldb + n0 + c * 8);
    }
}

__global__ __launch_bounds__(256, 2)
void gemm_h_kernel(const __half* __restrict__ A, const __half* __restrict__ B,
                   const float* __restrict__ bias,
                   void* __restrict__ Cv, int ldc,
                   void* __restrict__ C2v, int ldc2, int nsplit,
                   int K, int lda, int ldb, int fp32out, float cscale, int mbase)
{
    extern __shared__ char smem_raw[];
    uint32_t sb = (smem_u32(smem_raw) + 1023u) & ~1023u;

    const int tid  = threadIdx.x;
    const int wid  = tid >> 5;
    const int lane = tid & 31;
    const int wm   = wid & 3;
    const int wn   = wid >> 2;
    const int g    = lane >> 2;
    const int tig  = lane & 3;
    const int m0 = (blockIdx.y + mbase) * 128;
    const int n0 = blockIdx.x * 128;

    float acc[2][8][4];
#pragma unroll
    for (int mt = 0; mt < 2; mt++)
#pragma unroll
        for (int nt = 0; nt < 8; nt++)
#pragma unroll
            for (int e = 0; e < 4; e++) acc[mt][nt][e] = 0.f;

    const uint32_t a_row  = wm * 32 + (lane & 15);
    const uint32_t a_chb  = lane >> 4;
    const uint32_t bt_row = (((lane >> 3) & 1) << 3) + (lane & 7);
    const uint32_t bt_chb = lane >> 4;

    const int S = K >> 6;

    gemm_load_stage(sb,          A, B, lda, ldb, m0, n0, 0,  tid); CP_COMMIT();
    gemm_load_stage(sb + GSTAGE, A, B, lda, ldb, m0, n0, 64, tid); CP_COMMIT();

    for (int s = 0; s < S; s++) {
        CP_WAIT1();
        __syncthreads();
        if (s + 2 < S) {
            int bi = s + 2 - 3 * ((s + 2) / 3);
            gemm_load_stage(sb + bi * GSTAGE,
                            A, B, lda, ldb, m0, n0, (s + 2) * 64, tid);
        }
        CP_COMMIT();

        const int sbi = s - 3 * (s / 3);
        const uint32_t bA = sb + sbi * GSTAGE;
        const uint32_t bB = bA + 16384;

#pragma unroll
        for (int kt = 0; kt < 4; kt++) {
            uint32_t af[2][4], bf[8][2];
#pragma unroll
            for (int mt = 0; mt < 2; mt++)
                LDSM_X4(af[mt][0], af[mt][1], af[mt][2], af[mt][3],
                        bA + swz128(a_row + mt * 16, kt * 2 + a_chb));
#pragma unroll
            for (int np = 0; np < 4; np++) {
                uint32_t r0, r1, r2, r3;
                LDSM_X4_T(r0, r1, r2, r3,
                          bB + swz256(kt * 16 + bt_row,
                                      (uint32_t)(wn * 8 + np * 2) + bt_chb));
                bf[2 * np][0] = r0; bf[2 * np][1] = r1;
                bf[2 * np + 1][0] = r2; bf[2 * np + 1][1] = r3;
            }
#pragma unroll
            for (int mt = 0; mt < 2; mt++)
#pragma unroll
                for (int nt = 0; nt < 8; nt++)
                    MMA16816(acc[mt][nt], af[mt], bf[nt][0], bf[nt][1]);
        }
    }

    // Epilogue
#pragma unroll
    for (int mt = 0; mt < 2; mt++) {
#pragma unroll
        for (int nt = 0; nt < 8; nt++) {
            int row = m0 + wm * 32 + mt * 16 + g;
            int col = n0 + wn * 64 + nt * 8 + 2 * tig;
            float* a = acc[mt][nt];
            if (fp32out) {
                float* C = (float*)Cv;
                float b0 = bias ? bias[col]     : 0.f;
                float b1 = bias ? bias[col + 1] : 0.f;
                *(float2*)(C + (size_t)row * ldc + col) =
                    make_float2(a[0] + b0, a[1] + b1);
                *(float2*)(C + (size_t)(row + 8) * ldc + col) =
                    make_float2(a[2] + b0, a[3] + b1);
            } else if (col < nsplit) {
                __half* C = (__half*)Cv;
                *(uint32_t*)(C + (size_t)row * ldc + col) =
                    packh2(a[0] * cscale, a[1] * cscale);
                *(uint32_t*)(C + (size_t)(row + 8) * ldc + col) =
                    packh2(a[2] * cscale, a[3] * cscale);
            } else {
                __half* C = (__half*)C2v;
                int c2 = col - nsplit;
                *(uint32_t*)(C + (size_t)row * ldc2 + c2)       = packh2(a[0], a[1]);
                *(uint32_t*)(C + (size_t)(row + 8) * ldc2 + c2) = packh2(a[2], a[3]);
            }
        }
    }
}

// ---------------------------------------------------------------------------
// Flash attention, fp16 mma.sync, causal. BQ=128, BK=128, 8 warps x 16 rows.
// S = QK^T with fp16 ACCUMULATION (2x MMA rate; q pre-scaled so |S|<~2).
// Static-shift softmax directly on packed half2 S fragments.
// PV + row-sum MMAs keep fp32 accumulators.
// ---------------------------------------------------------------------------
#define ATTN_SMEM (163840 + 1024)

__global__ __launch_bounds__(256, 1)
void attn_h_kernel(const __half* __restrict__ qh, const __half* __restrict__ kvh,
                   __half* __restrict__ ctxh, int bsel)
{
    extern __shared__ char smem_raw[];
    uint32_t sb = (smem_u32(smem_raw) + 1023u) & ~1023u;
    const uint32_t Qs  = sb;
    const uint32_t KB0 = sb + 32768;
    const uint32_t VB0 = sb + 65536;
    const uint32_t KB1 = sb + 98304;
    const uint32_t VB1 = sb + 131072;

    const int tid  = threadIdx.x;
    const int wq   = tid >> 5;
    const int lane = tid & 31;
    const int g    = lane >> 2;
    const int tig  = lane & 3;
    const int qb = gridDim.x - 1 - blockIdx.x;   // heavy tiles first
    const int h  = blockIdx.y;
    const int b  = bsel;

    const int qrow0 = qb * 128;
    const size_t qrowg  = (size_t)b * SEQ + qrow0;
    const size_t kvrowg = (size_t)b * SEQ;

#pragma unroll
    for (int i = 0; i < 8; i++) {
        int f = tid + i * 256;
        int r = f >> 4, c = f & 15;
        CP_ASYNC16(Qs + swz256(r, c),
                   qh + (qrowg + r) * D_OUTC + h * HDIM + c * 8);
        const __half* src = kvh + (kvrowg + r) * (2 * D_OUTC) + h * HDIM + c * 8;
        CP_ASYNC16(KB0 + swz256(r, c), src);
        CP_ASYNC16(VB0 + swz256(r, c), src + D_OUTC);
    }
    CP_COMMIT();

    float ob[16][4];
#pragma unroll
    for (int nt = 0; nt < 16; nt++)
#pragma unroll
        for (int e = 0; e < 4; e++) ob[nt][e] = 0.f;
    float lacc[4] = {0.f, 0.f, 0.f, 0.f};
    uint32_t qf[8][4];
    const int grA = qrow0 + wq * 16 + g;
    const int grB = grA + 8;

    const uint32_t k_rowb = ((lane >> 4) << 3) + (lane & 7);
    const uint32_t k_chb  = (lane >> 3) & 1;
    const uint32_t v_rowb = (((lane >> 3) & 1) << 3) + (lane & 7);
    const uint32_t v_chb  = lane >> 4;

    for (int kb = 0; kb <= qb; kb++) {
        __syncthreads();
        if (kb + 1 <= qb) {
            const uint32_t nK = ((kb + 1) & 1) ? KB1 : KB0;
            const uint32_t nV = ((kb + 1) & 1) ? VB1 : VB0;
#pragma unroll
            for (int i = 0; i < 8; i++) {
                int f = tid + i * 256;
                int r = f >> 4, c = f & 15;
                const __half* src = kvh + (kvrowg + (size_t)(kb + 1) * 128 + r) * (2 * D_OUTC)
                                    + h * HDIM + c * 8;
                CP_ASYNC16(nK + swz256(r, c), src);
                CP_ASYNC16(nV + swz256(r, c), src + D_OUTC);
            }
        }
        CP_COMMIT();
        CP_WAIT1();
        __syncthreads();

        if (kb == 0) {
#pragma unroll
            for (int kt = 0; kt < 8; kt++) {
                uint32_t row = wq * 16 + (lane & 15);
                uint32_t ch  = kt * 2 + (lane >> 4);
                LDSM_X4(qf[kt][0], qf[kt][1], qf[kt][2], qf[kt][3],
                        Qs + swz256(row, ch));
            }
        }

        const uint32_t Kbuf = (kb & 1) ? KB1 : KB0;
        const uint32_t Vbuf = (kb & 1) ? VB1 : VB0;

        // ---- S = Q @ K^T (fp16 accum), pipelined LDSM ----
        // sch[nt][0] = {row g,  cols c0,c0+1} packed; sch[nt][1] = row g+8.
        uint32_t sch[16][2];
#pragma unroll
        for (int nt = 0; nt < 16; nt++) { sch[nt][0] = 0u; sch[nt][1] = 0u; }

        uint32_t kr[2][4];
        LDSM_X4(kr[0][0], kr[0][1], kr[0][2], kr[0][3],
                Kbuf + swz256(k_rowb, k_chb));
#pragma unroll
        for (int np = 0; np < 8; np++) {
#pragma unroll
            for (int kt = 0; kt < 8; kt++) {
                const int idx = np * 8 + kt;
                const int cur = idx & 1, nxt = cur ^ 1;
                if (idx < 63) {
                    const int ni = idx + 1;
                    const uint32_t nrow = (uint32_t)(ni >> 3) * 16 + k_rowb;
                    const uint32_t nch  = (uint32_t)(ni & 7) * 2 + k_chb;
                    LDSM_X4(kr[nxt][0], kr[nxt][1], kr[nxt][2], kr[nxt][3],
                            Kbuf + swz256(nrow, nch));
                }
                MMA16816_H(sch[2 * np],     qf[kt], kr[cur][0], kr[cur][1]);
                MMA16816_H(sch[2 * np + 1], qf[kt], kr[cur][2], kr[cur][3]);
            }
        }

        // causal mask on packed regs (diagonal block only; low half = col c0)
        if (kb == qb) {
#pragma unroll
            for (int nt = 0; nt < 16; nt++) {
                int c0 = kb * 128 + nt * 8 + 2 * tig;
                if (c0 > grA)          sch[nt][0] = (H_NINF << 16) | H_NINF;
                else if (c0 + 1 > grA) sch[nt][0] = (sch[nt][0] & 0xFFFFu) | (H_NINF << 16);
                if (c0 > grB)          sch[nt][1] = (H_NINF << 16) | H_NINF;
                else if (c0 + 1 > grB) sch[nt][1] = (sch[nt][1] & 0xFFFFu) | (H_NINF << 16);
            }
        }

        // P fragments: 2^(s - SHIFT) on packed half2
        uint32_t pa[8][4];
#pragma unroll
        for (int kt = 0; kt < 8; kt++) {
            pa[kt][0] = h2ex2(h2sub(sch[2 * kt][0],     H2_SHIFT));
            pa[kt][1] = h2ex2(h2sub(sch[2 * kt][1],     H2_SHIFT));
            pa[kt][2] = h2ex2(h2sub(sch[2 * kt + 1][0], H2_SHIFT));
            pa[kt][3] = h2ex2(h2sub(sch[2 * kt + 1][1], H2_SHIFT));
        }

        // row sums on the tensor pipe (fp32 accum): lacc += P @ ones
#pragma unroll
        for (int kt = 0; kt < 8; kt++)
            MMA16816(lacc, pa[kt], H2_ONES, H2_ONES);

        // ---- O += P @ V (fp32 accum), pipelined LDSM_T ----
        uint32_t vr[2][4];
        LDSM_X4_T(vr[0][0], vr[0][1], vr[0][2], vr[0][3],
                  Vbuf + swz256(v_rowb, v_chb));
#pragma unroll
        for (int np = 0; np < 8; np++) {
#pragma unroll
            for (int kt = 0; kt < 8; kt++) {
                const int idx = np * 8 + kt;
                const int cur = idx & 1, nxt = cur ^ 1;
                if (idx < 63) {
                    const int ni = idx + 1;
                    const uint32_t nrow = (uint32_t)(ni & 7) * 16 + v_rowb;
                    const uint32_t nch  = (uint32_t)(ni >> 3) * 2 + v_chb;
                    LDSM_X4_T(vr[nxt][0], vr[nxt][1], vr[nxt][2], vr[nxt][3],
                              Vbuf + swz256(nrow, nch));
                }
                MMA16816(ob[2 * np],     pa[kt], vr[cur][0], vr[cur][1]);
                MMA16816(ob[2 * np + 1], pa[kt], vr[cur][2], vr[cur][3]);
            }
        }
    }

    const float invA = 1.f / lacc[0];
    const float invB = 1.f / lacc[2];
    const size_t rowA = (qrowg + wq * 16 + g) * D_OUTC + h * HDIM;
#pragma unroll
    for (int nt = 0; nt < 16; nt++) {
        int col = nt * 8 + 2 * tig;
        *(uint32_t*)(ctxh + rowA + col) =
            packh2(ob[nt][0] * invA, ob[nt][1] * invA);
        *(uint32_t*)(ctxh + rowA + 8 * D_OUTC + col) =
            packh2(ob[nt][2] * invB, ob[nt][3] * invB);
    }
}

// ---------------------------------------------------------------------------
// fp32 -> fp16 convert-copy (coalesced; optional column restack)
// ---------------------------------------------------------------------------
__global__ void conv_copy_h(const float* __restrict__ in,
                            __half* __restrict__ out,
                            int C, int ldout, int co, int total)
{
    int i = (blockIdx.x * 256 + threadIdx.x) * 4;
    if (i < total) {
        float4 v = *reinterpret_cast<const float4*>(in + i);
        int r = i / C, c = i - r * C;
        __half2* o = reinterpret_cast<__half2*>(out + (size_t)r * ldout + co + c);
        o[0] = __floats2half2_rn(v.x, v.y);
        o[1] = __floats2half2_rn(v.z, v.w);
    }
}

// ---------------------------------------------------------------------------
// Launch: two per-batch chains on two streams (exact R12 topology)
// ---------------------------------------------------------------------------
extern "C" void kernel_launch(void* const* d_in, const int* in_sizes, int n_in,
                              void* d_out, int out_size)
{
    const float* x    = (const float*)d_in[0];
    const float* Wq   = (const float*)d_in[1];
    const float* Wdkv = (const float*)d_in[2];
    const float* Wukv = (const float*)d_in[3];
    const float* Wout = (const float*)d_in[4];
    const float* bout = (const float*)d_in[5];
    float* out = (float*)d_out;

    __half *xh, *qh, *lath, *kvh, *ctxh, *wqd, *wukv, *wout;
    cudaGetSymbolAddress((void**)&xh,   g_xh);
    cudaGetSymbolAddress((void**)&qh,   g_qh);
    cudaGetSymbolAddress((void**)&lath, g_lath);
    cudaGetSymbolAddress((void**)&kvh,  g_kvh);
    cudaGetSymbolAddress((void**)&ctxh, g_ctxh);
    cudaGetSymbolAddress((void**)&wqd,  g_wqd);
    cudaGetSymbolAddress((void**)&wukv, g_wukv);
    cudaGetSymbolAddress((void**)&wout, g_wout);

    static cudaStream_t s1 = nullptr, s2 = nullptr;
    static cudaEvent_t e0, e_wqd, e_ukv, e_wout, e_d1, e_d2;
    if (!s1) {
        cudaStreamCreateWithFlags(&s1, cudaStreamNonBlocking);
        cudaStreamCreateWithFlags(&s2, cudaStreamNonBlocking);
        cudaEventCreateWithFlags(&e0,     cudaEventDisableTiming);
        cudaEventCreateWithFlags(&e_wqd,  cudaEventDisableTiming);
        cudaEventCreateWithFlags(&e_ukv,  cudaEventDisableTiming);
        cudaEventCreateWithFlags(&e_wout, cudaEventDisableTiming);
        cudaEventCreateWithFlags(&e_d1,   cudaEventDisableTiming);
        cudaEventCreateWithFlags(&e_d2,   cudaEventDisableTiming);
        cudaFuncSetAttribute(gemm_h_kernel,
                             cudaFuncAttributeMaxDynamicSharedMemorySize, GEMM_SMEM);
        cudaFuncSetAttribute(attn_h_kernel,
                             cudaFuncAttributeMaxDynamicSharedMemorySize, ATTN_SMEM);
    }

    const int HM = MTOT / 2;                 // rows per batch = 2048
    const int HT = HM / 128;                 // 16 M-tiles per batch
    const int HE = HM * D_INC;               // x elements per batch

    // Fork both streams off the capture (null) stream
    cudaEventRecord(e0, 0);
    cudaStreamWaitEvent(s1, e0, 0);
    cudaStreamWaitEvent(s2, e0, 0);

    // ---- S1 front: weights for proj, then batch-0 x ----
    conv_copy_h<<<(D_INC * D_OUTC) / 1024, 256, 0, s1>>>(
        Wq, wqd, D_OUTC, D_OUTC + LATENT, 0, D_INC * D_OUTC);
    conv_copy_h<<<(D_INC * LATENT) / 1024, 256, 0, s1>>>(
        Wdkv, wqd, LATENT, D_OUTC + LATENT, D_OUTC, D_INC * LATENT);
    cudaEventRecord(e_wqd, s1);
    conv_copy_h<<<HE / 1024, 256, 0, s1>>>(x, xh, D_INC, D_INC, 0, HE);

    // ---- S2 front: batch-1 x + other weights ----
    conv_copy_h<<<HE / 1024, 256, 0, s2>>>(x + HE, xh + HE, D_INC, D_INC, 0, HE);
    conv_copy_h<<<(LATENT * 2 * D_OUTC) / 1024, 256, 0, s2>>>(
        Wukv, wukv, 2 * D_OUTC, 2 * D_OUTC, 0, LATENT * 2 * D_OUTC);
    cudaEventRecord(e_ukv, s2);
    conv_copy_h<<<(D_OUTC * D_INC) / 1024, 256, 0, s2>>>(
        Wout, wout, D_INC, D_INC, 0, D_OUTC * D_INC);
    cudaEventRecord(e_wout, s2);

    // ---- S1 chain (batch 0) ----
    gemm_h_kernel<<<dim3((D_OUTC + LATENT) / 128, HT), 256, GEMM_SMEM, s1>>>(
        xh, wqd, nullptr, qh, D_OUTC, lath, LATENT, D_OUTC,
        D_INC, D_INC, D_OUTC + LATENT, 0, QK_SCALE, 0);
    cudaStreamWaitEvent(s1, e_ukv, 0);
    gemm_h_kernel<<<dim3((2 * D_OUTC) / 128, HT), 256, GEMM_SMEM, s1>>>(
        lath, wukv, nullptr, kvh, 2 * D_OUTC, nullptr, 0, 1 << 30,
        LATENT, LATENT, 2 * D_OUTC, 0, 1.0f, 0);
    attn_h_kernel<<<dim3(HT, NHEADS, 1), 256, ATTN_SMEM, s1>>>(qh, kvh, ctxh, 0);
    cudaStreamWaitEvent(s1, e_wout, 0);
    gemm_h_kernel<<<dim3(D_INC / 128, HT), 256, GEMM_SMEM, s1>>>(
        ctxh, wout, bout, out, D_INC, nullptr, 0, 1 << 30,
        D_OUTC, D_OUTC, D_INC, 1, 1.0f, 0);
    cudaEventRecord(e_d1, s1);

    // ---- S2 chain (batch 1) ----
    cudaStreamWaitEvent(s2, e_wqd, 0);
    gemm_h_kernel<<<dim3((D_OUTC + LATENT) / 128, HT), 256, GEMM_SMEM, s2>>>(
        xh, wqd, nullptr, qh, D_OUTC, lath, LATENT, D_OUTC,
        D_INC, D_INC, D_OUTC + LATENT, 0, QK_SCALE, HT);
    gemm_h_kernel<<<dim3((2 * D_OUTC) / 128, HT), 256, GEMM_SMEM, s2>>>(
        lath, wukv, nullptr, kvh, 2 * D_OUTC, nullptr, 0, 1 << 30,
        LATENT, LATENT, 2 * D_OUTC, 0, 1.0f, HT);
    attn_h_kernel<<<dim3(HT, NHEADS, 1), 256, ATTN_SMEM, s2>>>(qh, kvh, ctxh, 1);
    gemm_h_kernel<<<dim3(D_INC / 128, HT), 256, GEMM_SMEM, s2>>>(
        ctxh, wout, bout, out, D_INC, nullptr, 0, 1 << 30,
        D_OUTC, D_OUTC, D_INC, 1, 1.0f, HT);
    cudaEventRecord(e_d2, s2);

    // Join back into the capture stream
    cudaStreamWaitEvent(0, e_d1, 0);
    cudaStreamWaitEvent(0, e_d2, 0);
}